// round 8
// baseline (speedup 1.0000x reference)
#include <cuda_runtime.h>
#include <math.h>

#define NB    128
#define NTH   512
#define BB    64
#define TT    512
#define IND   512
#define XD    1024
#define OUTD  256

#define WS_STRIDE  68
#define WS_PHASE   (128 * WS_STRIDE)           // 8704 floats per weight tile
// As2: dup-A staging, group-padded: offset(k) = k*132 + 8*(k>>4), + 2*row
#define A_OFF(k)   ((k) * 132 + (((k) >> 4) << 3))
#define AS2_SIZE   (128 * 132 + 8 * 8 + 8)      // 16968 floats (padded)
#define SMEM_FLOATS (4 * WS_PHASE + AS2_SIZE)   // 34816 + 16968 = 51784
#define SMEM_BYTES  (SMEM_FLOATS * 4)           // 207136 (< 227KB carveout)

typedef unsigned long long ull;

#define FMA2(c, a, b) asm("fma.rn.f32x2 %0, %1, %2, %0;" : "+l"(c) : "l"(a), "l"(b))
#define UNPK(c, lo, hi) asm("mov.b64 {%0, %1}, %2;" : "=f"(lo), "=f"(hi) : "l"(c))

// ------------------------- device scratch ---------------------------------
__device__ float g_actin[(size_t)BB * TT * XD];     // [t*64+b][XD]
__device__ float g_P[(size_t)BB * TT * XD];         // [t*64+b][XD]
__device__ float g_h3all[(size_t)TT * BB * XD];     // [t][b][XD]
__device__ float g_part[(size_t)4 * 16 * 8 * 4096]; // [phase][tile][sp][64*64]
__device__ float g_np[16 * 8 * 64];                 // [nt][slice][row] partial sumsq of rs
__device__ unsigned g_cnt[4 * 16 * 8];              // [phase][tile] monotonic, 32B apart
__device__ unsigned g_barcnt;
__device__ unsigned g_bargen;

// ------------------------- scoped atomics ----------------------------------
__device__ __forceinline__ void red_release_add(unsigned* p) {
    asm volatile("red.release.gpu.add.u32 [%0], %1;" :: "l"(p), "r"(1u) : "memory");
}
__device__ __forceinline__ unsigned ld_acquire(const unsigned* p) {
    unsigned v;
    asm volatile("ld.acquire.gpu.u32 %0, [%1];" : "=r"(v) : "l"(p) : "memory");
    return v;
}

// ------------------------- branch-free fast activation ---------------------
__device__ __forceinline__ float rand_act(float v, int idx, float mx) {
    float en  = __expf(-v);
    float sig = __fdividef(1.0f, 1.0f + en);
    float th  = __fdividef(2.0f, 1.0f + en * en) - 1.0f;    // tanh(v)
    float sel = (v > 0.0f) ? 1.0507009873554805f * v
                           : 1.7580993408473766f * (__expf(v) - 1.0f);
    float r = (idx == 0) ? fmaxf(v, 0.0f)
            : (idx == 1) ? sig
            : (idx == 2) ? th
            : (idx == 3) ? ((v >= 0.0f) ? v : 0.1f * v)
            : sel;
    return fminf(r, mx);
}

__device__ __forceinline__ float4 act4(float4 v, int4 id, float4 mx) {
    return make_float4(rand_act(v.x, id.x, mx.x), rand_act(v.y, id.y, mx.y),
                       rand_act(v.z, id.z, mx.z), rand_act(v.w, id.w, mx.w));
}

// ------------------------- grid-wide barrier (pre/post loop only) ----------
__device__ __forceinline__ void gsync(unsigned& mygen) {
    __threadfence();
    __syncthreads();
    if (threadIdx.x == 0) {
        unsigned old = atomicAdd(&g_barcnt, 1u);
        if (old == NB - 1u) {
            g_barcnt = 0u;
            __threadfence();
            atomicAdd(&g_bargen, 1u);
        } else {
            while (((volatile unsigned*)&g_bargen)[0] == mygen) { __nanosleep(64); }
        }
    }
    __syncthreads();
    mygen += 1u;
}

// ------------------------- dataflow wait ------------------------------------
__device__ __forceinline__ void waitcnt(const unsigned* c0, const unsigned* c1, unsigned tgt) {
    if (threadIdx.x < 2) {
        const unsigned* p = threadIdx.x ? c1 : c0;
        while (ld_acquire(p) < tgt) {}
    }
    __syncthreads();
}

// ------------------------- staging ------------------------------------------
// A (64 rows x 128 k, global) -> As2 dup layout (precompute path)
__device__ __forceinline__ void stageA_dup(const float* __restrict__ A, int lda, float* As2) {
    const int row = threadIdx.x >> 3;
    const int f4  = threadIdx.x & 7;
    const float4* src = (const float4*)(A + (size_t)row * lda);
#pragma unroll
    for (int j = 0; j < 4; j++) {
        float4 v = __ldcg(&src[f4 + 8 * j]);
        const int kk = (f4 + 8 * j) << 2;
        float* dst = As2 + A_OFF(kk) + 2 * row;
        *(float2*)(dst + 0 * 132) = make_float2(v.x, v.x);
        *(float2*)(dst + 1 * 132) = make_float2(v.y, v.y);
        *(float2*)(dst + 2 * 132) = make_float2(v.z, v.z);
        *(float2*)(dst + 3 * 132) = make_float2(v.w, v.w);
    }
}

// B (64 rows x 128 k, row-major, constant) -> Bs[k][row], stride 68
__device__ __forceinline__ void stageB_T(const float* __restrict__ B, int ldb, float* Bs) {
    const int row = threadIdx.x >> 3;
    const int f4  = threadIdx.x & 7;
    const float4* src = (const float4*)(B + (size_t)row * ldb);
#pragma unroll
    for (int j = 0; j < 4; j++) {
        float4 v = __ldg(&src[f4 + 8 * j]);
        const int k = (f4 + 8 * j) << 2;
        Bs[(size_t)(k + 0) * WS_STRIDE + row] = v.x;
        Bs[(size_t)(k + 1) * WS_STRIDE + row] = v.y;
        Bs[(size_t)(k + 2) * WS_STRIDE + row] = v.z;
        Bs[(size_t)(k + 3) * WS_STRIDE + row] = v.w;
    }
}

// stage 16 values (cols k=16*f4..+15) as dup pairs into As2
__device__ __forceinline__ void stage_vals(float* As2, const float val[16], int row, int f4) {
    float* dst = As2 + A_OFF(16 * f4) + 2 * row;
#pragma unroll
    for (int j = 0; j < 16; j++)
        *(float2*)(dst + j * 132) = make_float2(val[j], val[j]);
}

// ------------------------- packed-f32x2 inner GEMM (K=128) -----------------
__device__ __forceinline__ void gemm_sh(const float* As2, const float* Bsh,
                                        ull& c00, ull& c01, ull& c10, ull& c11,
                                        int tx, int ty) {
    const float* bp = Bsh + (tx << 2);
#pragma unroll
    for (int kg = 0; kg < 8; kg++) {
        const float* ap = As2 + kg * (16 * 132 + 8) + (ty << 2);
        const float* bq = bp + (size_t)kg * 16 * WS_STRIDE;
#pragma unroll
        for (int u = 0; u < 16; u++) {
            ulonglong2 a = *(const ulonglong2*)(ap + u * 132);
            ulonglong2 b = *(const ulonglong2*)(bq + (size_t)u * WS_STRIDE);
            FMA2(c00, a.x, b.x); FMA2(c01, a.x, b.y);
            FMA2(c10, a.y, b.x); FMA2(c11, a.y, b.y);
        }
    }
}

__device__ __forceinline__ void unpack_acc(ull c00, ull c01, ull c10, ull c11,
                                           float acc[2][4]) {
    UNPK(c00, acc[0][0], acc[0][1]); UNPK(c01, acc[0][2], acc[0][3]);
    UNPK(c10, acc[1][0], acc[1][1]); UNPK(c11, acc[1][2], acc[1][3]);
}

// ------------------------- chunked full-K task GEMM (precompute/output) ----
__device__ __forceinline__ void gemm_task(const float* A, int lda,
                                          const float* B, int ldb,
                                          int nchunk, float acc[2][4],
                                          float* As2, float* Bs, int tx, int ty) {
    ull c00 = 0, c01 = 0, c10 = 0, c11 = 0;
    for (int c = 0; c < nchunk; c++) {
        stageA_dup(A + (c << 7), lda, As2);
        stageB_T(B + (c << 7), ldb, Bs);
        __syncthreads();
        gemm_sh(As2, Bs, c00, c01, c10, c11, tx, ty);
        __syncthreads();
    }
    unpack_acc(c00, c01, c10, c11, acc);
}

// ------------------------- consumer-side slab reduction --------------------
// Sum the 8 k-split slabs of the tile covering this thread's 16 columns.
// Fixed order -> bit-deterministic across all redundant consumers.
__device__ __forceinline__ void reduce_slabs(int phase, int sp, int row, int f4,
                                             float val[16]) {
    const int tile = 2 * sp + (f4 >> 2);
    const float* base = g_part + ((size_t)(phase * 16 + tile) * 8) * 4096
                      + row * 64 + (f4 & 3) * 16;
    float4 a0 = make_float4(0.f, 0.f, 0.f, 0.f), a1 = a0, a2 = a0, a3 = a0;
#pragma unroll
    for (int sl = 0; sl < 8; sl++) {
        const float4* p = (const float4*)(base + (size_t)sl * 4096);
        float4 v0 = __ldcg(p + 0), v1 = __ldcg(p + 1);
        float4 v2 = __ldcg(p + 2), v3 = __ldcg(p + 3);
        a0.x += v0.x; a0.y += v0.y; a0.z += v0.z; a0.w += v0.w;
        a1.x += v1.x; a1.y += v1.y; a1.z += v1.z; a1.w += v1.w;
        a2.x += v2.x; a2.y += v2.y; a2.z += v2.z; a2.w += v2.w;
        a3.x += v3.x; a3.y += v3.y; a3.z += v3.z; a3.w += v3.w;
    }
    val[0]=a0.x; val[1]=a0.y; val[2]=a0.z; val[3]=a0.w;
    val[4]=a1.x; val[5]=a1.y; val[6]=a1.z; val[7]=a1.w;
    val[8]=a2.x; val[9]=a2.y; val[10]=a2.z; val[11]=a2.w;
    val[12]=a3.x; val[13]=a3.y; val[14]=a3.z; val[15]=a3.w;
}

// gemm vs persistent weight tile, store slab, bump counter (release)
__device__ __forceinline__ void gemm_publish(int phase, int nt, int sp,
                                             const float* wsp, const float* as2,
                                             int tx, int ty) {
    ull c00 = 0, c01 = 0, c10 = 0, c11 = 0;
    gemm_sh(as2, wsp, c00, c01, c10, c11, tx, ty);
    float acc[2][4];
    unpack_acc(c00, c01, c10, c11, acc);
    float* slab = g_part + ((size_t)(phase * 16 + nt) * 8 + sp) * 4096;
#pragma unroll
    for (int i = 0; i < 2; i++) {
        float4 v = make_float4(acc[i][0], acc[i][1], acc[i][2], acc[i][3]);
        __stcg((float4*)&slab[((ty << 1) + i) * 64 + (tx << 2)], v);
    }
    __syncthreads();
    if (threadIdx.x == 0) red_release_add(&g_cnt[(phase * 16 + nt) * 8]);
}

// ------------------------- main persistent kernel --------------------------
__global__ void __launch_bounds__(NTH, 1)
bnn_kernel(const float* __restrict__ x,
           const float* __restrict__ Wi,  const float* __restrict__ bi,
           const float* __restrict__ Wh1, const float* __restrict__ bh1,
           const float* __restrict__ Wh2, const float* __restrict__ bh2,
           const float* __restrict__ Wh3, const float* __restrict__ bh3,
           const float* __restrict__ Wo,  const float* __restrict__ bo,
           const float* __restrict__ Wr,  const float* __restrict__ br,
           const float* __restrict__ max_in,  const float* __restrict__ max_h1,
           const float* __restrict__ max_h2,  const float* __restrict__ max_h3,
           const float* __restrict__ max_out, const float* __restrict__ max_rec,
           const int* __restrict__ idx_in,  const int* __restrict__ idx_h1,
           const int* __restrict__ idx_h2,  const int* __restrict__ idx_h3,
           const int* __restrict__ idx_out, const int* __restrict__ idx_rec,
           float* __restrict__ out) {
    extern __shared__ float smem[];
    float* ws  = smem;                    // 4 persistent loop weight tiles / scratch
    float* as2 = smem + 4 * WS_PHASE;

    const int bid = blockIdx.x;
    const int tid = threadIdx.x;
    const int tx  = tid & 15;             // gemm: 4 output cols
    const int ty  = tid >> 4;             // gemm: 2 output rows
    const int row = tid >> 3;             // consumer: 0..63
    const int f4  = tid & 7;              // consumer: 16-col chunk

    unsigned mygen = ((volatile unsigned*)&g_bargen)[0];

    // ---- init (every launch) ----
    if (bid == 0) {
        for (int j = tid; j < 4 * 16 * 8; j += NTH) g_cnt[j] = 0u;
        for (int j = tid; j < 16 * 8 * 64; j += NTH) g_np[j] = 0.0f;
    }
    gsync(mygen);

    // ================= Phase A: actin = act(x @ Wi^T + bi), permuted =======
    for (int task = bid; task < 512 * 16; task += NB) {
        const int rt = task >> 4, nt2 = task & 15;
        float acc[2][4];
        gemm_task(x + (size_t)rt * 64 * IND, IND,
                  Wi + (size_t)(nt2 << 6) * IND, IND, 4, acc, as2, ws, tx, ty);
        const int col0 = (nt2 << 6) + (tx << 2);
        const int4   id4 = __ldg((const int4*)&idx_in[col0]);
        const float4 mx4 = __ldg((const float4*)&max_in[col0]);
        const float4 b4  = __ldg((const float4*)&bi[col0]);
#pragma unroll
        for (int i = 0; i < 2; i++) {
            const int g = rt * 64 + (ty << 1) + i;
            const int b = g >> 9, t = g & 511;
            float4 v = make_float4(acc[i][0] + b4.x, acc[i][1] + b4.y,
                                   acc[i][2] + b4.z, acc[i][3] + b4.w);
            v = act4(v, id4, mx4);
            __stcg((float4*)&g_actin[(size_t)(t * BB + b) * XD + col0], v);
        }
    }
    gsync(mygen);

    // ================= Phase B: P = actin @ Wh1a^T + bh1 ===================
    for (int task = bid; task < 512 * 16; task += NB) {
        const int rt = task >> 4, nt2 = task & 15;
        float acc[2][4];
        gemm_task(g_actin + (size_t)rt * 64 * XD, XD,
                  Wh1 + (size_t)(nt2 << 6) * (2 * XD), 2 * XD, 8, acc, as2, ws, tx, ty);
        const int col0 = (nt2 << 6) + (tx << 2);
        const float4 b4 = __ldg((const float4*)&bh1[col0]);
#pragma unroll
        for (int i = 0; i < 2; i++) {
            const int r = rt * 64 + (ty << 1) + i;
            float4 v = make_float4(acc[i][0] + b4.x, acc[i][1] + b4.y,
                                   acc[i][2] + b4.z, acc[i][3] + b4.w);
            __stcg((float4*)&g_P[(size_t)r * XD + col0], v);
        }
    }
    gsync(mygen);

    // ================= preload persistent loop weights =====================
    const int nt = bid >> 3;              // output tile 0..15
    const int sp = bid & 7;               // k-split 0..7
    const int n0 = nt << 6;
    const int k0 = sp << 7;
    const int c0 = k0 + 16 * f4;          // this thread's first column

    stageB_T(Wh1 + (size_t)n0 * (2 * XD) + XD + k0, 2 * XD, ws + 0 * WS_PHASE);
    stageB_T(Wh2 + (size_t)n0 * XD + k0,            XD,     ws + 1 * WS_PHASE);
    stageB_T(Wh3 + (size_t)n0 * XD + k0,            XD,     ws + 2 * WS_PHASE);
    stageB_T(Wr  + (size_t)n0 * XD + k0,            XD,     ws + 3 * WS_PHASE);
    __syncthreads();

    const unsigned* p1a = &g_cnt[(3 * 16 + 2 * sp) * 8];
    const unsigned* p1b = &g_cnt[(3 * 16 + 2 * sp + 1) * 8];
    const unsigned* p2a = &g_cnt[(0 * 16 + 2 * sp) * 8];
    const unsigned* p2b = &g_cnt[(0 * 16 + 2 * sp + 1) * 8];
    const unsigned* p3a = &g_cnt[(1 * 16 + 2 * sp) * 8];
    const unsigned* p3b = &g_cnt[(1 * 16 + 2 * sp + 1) * 8];
    const unsigned* p4a = &g_cnt[(2 * 16 + 2 * sp) * 8];
    const unsigned* p4b = &g_cnt[(2 * 16 + 2 * sp + 1) * 8];

    // ================= time loop: ONE hop per phase ========================
    for (int s = 0; s < TT; s++) {
        const unsigned e = (unsigned)(s + 1);
        float val[16];

        // ---- Phase 1: rs = act(phase4-slabs + br); slab = rs @ Wh1b^T ----
        if (s == 0) {
#pragma unroll
            for (int j = 0; j < 16; j++) val[j] = 0.0f;   // rs0 = 0 exactly
        } else {
            waitcnt(p1a, p1b, 8u * (unsigned)s);
            reduce_slabs(3, sp, row, f4, val);
            float ssq = 0.0f;
#pragma unroll
            for (int g = 0; g < 4; g++) {
                const int c = c0 + 4 * g;
                float4 b4  = __ldg((const float4*)&br[c]);
                int4   id4 = __ldg((const int4*)&idx_rec[c]);
                float4 mx4 = __ldg((const float4*)&max_rec[c]);
                val[4*g+0] = rand_act(val[4*g+0] + b4.x, id4.x, mx4.x);
                val[4*g+1] = rand_act(val[4*g+1] + b4.y, id4.y, mx4.y);
                val[4*g+2] = rand_act(val[4*g+2] + b4.z, id4.z, mx4.z);
                val[4*g+3] = rand_act(val[4*g+3] + b4.w, id4.w, mx4.w);
                ssq += val[4*g+0]*val[4*g+0] + val[4*g+1]*val[4*g+1]
                     + val[4*g+2]*val[4*g+2] + val[4*g+3]*val[4*g+3];
            }
            ssq += __shfl_xor_sync(0xffffffffu, ssq, 1, 8);
            ssq += __shfl_xor_sync(0xffffffffu, ssq, 2, 8);
            ssq += __shfl_xor_sync(0xffffffffu, ssq, 4, 8);
            if (f4 == 0) __stcg(&g_np[(nt * 8 + sp) * 64 + row], ssq);
        }
        stage_vals(as2, val, row, f4);
        __syncthreads();
        gemm_publish(0, nt, sp, ws + 0 * WS_PHASE, as2, tx, ty);

        // ---- Phase 2: h1 = act(red*rinv + P[s]); slab = h1 @ Wh2^T ----
        waitcnt(p2a, p2b, 8u * e);
        reduce_slabs(0, sp, row, f4, val);
        {
            float ss = 0.0f;
#pragma unroll
            for (int sl = 0; sl < 8; sl++)
                ss += __ldcg(&g_np[((2 * sp) * 8 + sl) * 64 + row]);
            const float rinv = __fdividef(1.0f, fmaxf(__fsqrt_rn(ss), 1e-12f));
            const float* Pt = g_P + ((size_t)s * BB + row) * XD + c0;
#pragma unroll
            for (int g = 0; g < 4; g++) {
                const int c = c0 + 4 * g;
                float4 p4  = __ldcg((const float4*)(Pt + 4 * g));
                int4   id4 = __ldg((const int4*)&idx_h1[c]);
                float4 mx4 = __ldg((const float4*)&max_h1[c]);
                val[4*g+0] = rand_act(val[4*g+0] * rinv + p4.x, id4.x, mx4.x);
                val[4*g+1] = rand_act(val[4*g+1] * rinv + p4.y, id4.y, mx4.y);
                val[4*g+2] = rand_act(val[4*g+2] * rinv + p4.z, id4.z, mx4.z);
                val[4*g+3] = rand_act(val[4*g+3] * rinv + p4.w, id4.w, mx4.w);
            }
        }
        stage_vals(as2, val, row, f4);
        __syncthreads();
        gemm_publish(1, nt, sp, ws + 1 * WS_PHASE, as2, tx, ty);

        // ---- Phase 3: h2 = act(red + bh2); slab = h2 @ Wh3^T ----
        waitcnt(p3a, p3b, 8u * e);
        reduce_slabs(1, sp, row, f4, val);
#pragma unroll
        for (int g = 0; g < 4; g++) {
            const int c = c0 + 4 * g;
            float4 b4  = __ldg((const float4*)&bh2[c]);
            int4   id4 = __ldg((const int4*)&idx_h2[c]);
            float4 mx4 = __ldg((const float4*)&max_h2[c]);
            val[4*g+0] = rand_act(val[4*g+0] + b4.x, id4.x, mx4.x);
            val[4*g+1] = rand_act(val[4*g+1] + b4.y, id4.y, mx4.y);
            val[4*g+2] = rand_act(val[4*g+2] + b4.z, id4.z, mx4.z);
            val[4*g+3] = rand_act(val[4*g+3] + b4.w, id4.w, mx4.w);
        }
        stage_vals(as2, val, row, f4);
        __syncthreads();
        gemm_publish(2, nt, sp, ws + 2 * WS_PHASE, as2, tx, ty);

        // ---- Phase 4: h3 = act(red + bh3); slab = h3 @ Wr^T ----
        waitcnt(p4a, p4b, 8u * e);
        reduce_slabs(2, sp, row, f4, val);
#pragma unroll
        for (int g = 0; g < 4; g++) {
            const int c = c0 + 4 * g;
            float4 b4  = __ldg((const float4*)&bh3[c]);
            int4   id4 = __ldg((const int4*)&idx_h3[c]);
            float4 mx4 = __ldg((const float4*)&max_h3[c]);
            val[4*g+0] = rand_act(val[4*g+0] + b4.x, id4.x, mx4.x);
            val[4*g+1] = rand_act(val[4*g+1] + b4.y, id4.y, mx4.y);
            val[4*g+2] = rand_act(val[4*g+2] + b4.z, id4.z, mx4.z);
            val[4*g+3] = rand_act(val[4*g+3] + b4.w, id4.w, mx4.w);
        }
        if (nt == 0) {      // materialize h3 for the output GEMM (one writer per column slice)
            float* h3t = g_h3all + ((size_t)s * BB + row) * XD + c0;
#pragma unroll
            for (int g = 0; g < 4; g++)
                __stcg((float4*)(h3t + 4 * g),
                       make_float4(val[4*g+0], val[4*g+1], val[4*g+2], val[4*g+3]));
        }
        stage_vals(as2, val, row, f4);
        __syncthreads();
        gemm_publish(3, nt, sp, ws + 3 * WS_PHASE, as2, tx, ty);
    }
    gsync(mygen);

    // ================= Output GEMM: y = act(H3 @ Wo^T + bo) ================
    for (int task = bid; task < 512 * 4; task += NB) {
        const int t = task >> 2, ot = task & 3;
        float acc[2][4];
        gemm_task(g_h3all + (size_t)t * BB * XD, XD,
                  Wo + (size_t)(ot << 6) * XD, XD, 8, acc, as2, ws, tx, ty);
        const int oc0 = (ot << 6) + (tx << 2);
        const int4   id4 = __ldg((const int4*)&idx_out[oc0]);
        const float4 mx4 = __ldg((const float4*)&max_out[oc0]);
        const float4 b4  = __ldg((const float4*)&bo[oc0]);
#pragma unroll
        for (int i = 0; i < 2; i++) {
            const int b = (ty << 1) + i;
            float4 v = make_float4(acc[i][0] + b4.x, acc[i][1] + b4.y,
                                   acc[i][2] + b4.z, acc[i][3] + b4.w);
            v = act4(v, id4, mx4);
            __stcg((float4*)&out[((size_t)b * TT + t) * OUTD + oc0], v);
        }
    }
}

// ------------------------- launch ------------------------------------------
extern "C" void kernel_launch(void* const* d_in, const int* in_sizes, int n_in,
                              void* d_out, int out_size) {
    const float* x       = (const float*)d_in[0];
    const float* Wi      = (const float*)d_in[1];
    const float* bi      = (const float*)d_in[2];
    const float* Wh1     = (const float*)d_in[3];
    const float* bh1     = (const float*)d_in[4];
    const float* Wh2     = (const float*)d_in[5];
    const float* bh2     = (const float*)d_in[6];
    const float* Wh3     = (const float*)d_in[7];
    const float* bh3     = (const float*)d_in[8];
    const float* Wo      = (const float*)d_in[9];
    const float* bo      = (const float*)d_in[10];
    const float* Wr      = (const float*)d_in[11];
    const float* br      = (const float*)d_in[12];
    const float* max_in  = (const float*)d_in[13];
    const float* max_h1  = (const float*)d_in[14];
    const float* max_h2  = (const float*)d_in[15];
    const float* max_h3  = (const float*)d_in[16];
    const float* max_out = (const float*)d_in[17];
    const float* max_rec = (const float*)d_in[18];
    const int*   idx_in  = (const int*)d_in[19];
    const int*   idx_h1  = (const int*)d_in[20];
    const int*   idx_h2  = (const int*)d_in[21];
    const int*   idx_h3  = (const int*)d_in[22];
    const int*   idx_out = (const int*)d_in[23];
    const int*   idx_rec = (const int*)d_in[24];

    static int configured = 0;
    if (!configured) {
        cudaFuncSetAttribute(bnn_kernel, cudaFuncAttributeMaxDynamicSharedMemorySize,
                             SMEM_BYTES);
        configured = 1;
    }

    bnn_kernel<<<NB, NTH, SMEM_BYTES>>>(x, Wi, bi, Wh1, bh1, Wh2, bh2, Wh3, bh3,
                                        Wo, bo, Wr, br,
                                        max_in, max_h1, max_h2, max_h3, max_out, max_rec,
                                        idx_in, idx_h1, idx_h2, idx_h3, idx_out, idx_rec,
                                        (float*)d_out);
}

// round 10
// speedup vs baseline: 1.0476x; 1.0476x over previous
#include <cuda_runtime.h>
#include <math.h>

#define NB    128
#define NTH   512
#define BB    64
#define TT    512
#define IND   512
#define XD    1024
#define OUTD  256

#define WS_STRIDE  68
#define WS_PHASE   (128 * WS_STRIDE)           // 8704 floats per weight tile
#define AS2_STRIDE 132
#define AS_STR     132                          // loop A staging stride (32 rows)
#define SMEM_FLOATS (4 * WS_PHASE + 128 * AS2_STRIDE)   // 51712
#define SMEM_BYTES  (SMEM_FLOATS * 4)                   // 206848

typedef unsigned long long ull;

#define FMA2(c, a, b) asm("fma.rn.f32x2 %0, %1, %2, %0;" : "+l"(c) : "l"(a), "l"(b))
#define UNPK(c, lo, hi) asm("mov.b64 {%0, %1}, %2;" : "=f"(lo), "=f"(hi) : "l"(c))

// ------------------------- device scratch ---------------------------------
__device__ float g_actin[(size_t)BB * TT * XD];     // [t*64+b][XD]
__device__ float g_P[(size_t)BB * TT * XD];         // [t*64+b][XD]  (bh1 folded in)
__device__ float g_h3all[(size_t)TT * BB * XD];     // [t][b][XD]
__device__ float g_h1[2 * 32 * XD];                 // per-chain h1
__device__ float g_h2[2 * 32 * XD];
__device__ float g_rs[2 * 32 * XD];
__device__ float g_np[2 * 32 * 16];                 // [chain][row][tile] sumsq of rs
__device__ float g_part[(size_t)2 * 4 * 16 * 8 * 2048]; // [chain][ph][tile][sp][32*64]
__device__ unsigned g_scnt[2 * 4 * 16 * 8];         // slab arrivals (monotonic), 32B apart
__device__ unsigned g_hcnt[2 * 4 * 16 * 8];         // h-ready epochs (monotonic), 32B apart
__device__ unsigned g_barcnt;
__device__ unsigned g_bargen;

// ------------------------- scoped atomics ----------------------------------
__device__ __forceinline__ unsigned atom_acqrel_add(unsigned* p) {
    unsigned o;
    asm volatile("atom.acq_rel.gpu.add.u32 %0, [%1], %2;"
                 : "=r"(o) : "l"(p), "r"(1u) : "memory");
    return o;
}
__device__ __forceinline__ void red_release_add(unsigned* p) {
    asm volatile("red.release.gpu.add.u32 [%0], %1;" :: "l"(p), "r"(1u) : "memory");
}
__device__ __forceinline__ unsigned ld_acquire(const unsigned* p) {
    unsigned v;
    asm volatile("ld.acquire.gpu.u32 %0, [%1];" : "=r"(v) : "l"(p) : "memory");
    return v;
}

// ------------------------- branch-free fast activation ---------------------
__device__ __forceinline__ float rand_act(float v, int idx, float mx) {
    float en  = __expf(-v);
    float sig = __fdividef(1.0f, 1.0f + en);
    float th  = __fdividef(2.0f, 1.0f + en * en) - 1.0f;
    float sel = (v > 0.0f) ? 1.0507009873554805f * v
                           : 1.7580993408473766f * (__expf(v) - 1.0f);
    float r = (idx == 0) ? fmaxf(v, 0.0f)
            : (idx == 1) ? sig
            : (idx == 2) ? th
            : (idx == 3) ? ((v >= 0.0f) ? v : 0.1f * v)
            : sel;
    return fminf(r, mx);
}

__device__ __forceinline__ float4 act4(float4 v, int4 id, float4 mx) {
    return make_float4(rand_act(v.x, id.x, mx.x), rand_act(v.y, id.y, mx.y),
                       rand_act(v.z, id.z, mx.z), rand_act(v.w, id.w, mx.w));
}

// ------------------------- grid-wide barrier (pre/post loop only) ----------
__device__ __forceinline__ void gsync(unsigned& mygen) {
    __threadfence();
    __syncthreads();
    if (threadIdx.x == 0) {
        unsigned old = atomicAdd(&g_barcnt, 1u);
        if (old == NB - 1u) {
            g_barcnt = 0u;
            __threadfence();
            atomicAdd(&g_bargen, 1u);
        } else {
            while (((volatile unsigned*)&g_bargen)[0] == mygen) { __nanosleep(64); }
        }
    }
    __syncthreads();
    mygen += 1u;
}

// ------------------------- dataflow wait ------------------------------------
__device__ __forceinline__ void waitcnt(const unsigned* c0, const unsigned* c1, unsigned tgt) {
    if (threadIdx.x < 2) {
        const unsigned* p = threadIdx.x ? c1 : c0;
        while (ld_acquire(p) < tgt) {}
    }
    __syncthreads();
}

// ------------------------- precompute helpers (FFMA2 path) -----------------
__device__ __forceinline__ void stageA_dup(const float* __restrict__ A, int lda, float* As2) {
    const int row = threadIdx.x >> 3;
    const int f4  = threadIdx.x & 7;
    const float4* src = (const float4*)(A + (size_t)row * lda);
#pragma unroll
    for (int j = 0; j < 4; j++) {
        float4 v = __ldcg(&src[f4 + 8 * j]);
        const int k = (f4 + 8 * j) << 2;
        *(float2*)(As2 + (size_t)(k + 0) * AS2_STRIDE + 2 * row) = make_float2(v.x, v.x);
        *(float2*)(As2 + (size_t)(k + 1) * AS2_STRIDE + 2 * row) = make_float2(v.y, v.y);
        *(float2*)(As2 + (size_t)(k + 2) * AS2_STRIDE + 2 * row) = make_float2(v.z, v.z);
        *(float2*)(As2 + (size_t)(k + 3) * AS2_STRIDE + 2 * row) = make_float2(v.w, v.w);
    }
}

__device__ __forceinline__ void stageB_T(const float* __restrict__ B, int ldb, float* Bs) {
    const int row = threadIdx.x >> 3;
    const int f4  = threadIdx.x & 7;
    const float4* src = (const float4*)(B + (size_t)row * ldb);
#pragma unroll
    for (int j = 0; j < 4; j++) {
        float4 v = __ldg(&src[f4 + 8 * j]);
        const int k = (f4 + 8 * j) << 2;
        Bs[(size_t)(k + 0) * WS_STRIDE + row] = v.x;
        Bs[(size_t)(k + 1) * WS_STRIDE + row] = v.y;
        Bs[(size_t)(k + 2) * WS_STRIDE + row] = v.z;
        Bs[(size_t)(k + 3) * WS_STRIDE + row] = v.w;
    }
}

__device__ __forceinline__ void gemm_sh(const float* As2, const float* Bsh,
                                        ull& c00, ull& c01, ull& c10, ull& c11,
                                        int tx, int ty) {
    const float* ap = As2 + (ty << 2);
    const float* bp = Bsh + (tx << 2);
#pragma unroll 8
    for (int k = 0; k < 128; k++) {
        ulonglong2 a = *(const ulonglong2*)(ap + (size_t)k * AS2_STRIDE);
        ulonglong2 b = *(const ulonglong2*)(bp + (size_t)k * WS_STRIDE);
        FMA2(c00, a.x, b.x); FMA2(c01, a.x, b.y);
        FMA2(c10, a.y, b.x); FMA2(c11, a.y, b.y);
    }
}

__device__ __forceinline__ void unpack_acc(ull c00, ull c01, ull c10, ull c11,
                                           float acc[2][4]) {
    UNPK(c00, acc[0][0], acc[0][1]); UNPK(c01, acc[0][2], acc[0][3]);
    UNPK(c10, acc[1][0], acc[1][1]); UNPK(c11, acc[1][2], acc[1][3]);
}

__device__ __forceinline__ void gemm_task(const float* A, int lda,
                                          const float* B, int ldb,
                                          int nchunk, float acc[2][4],
                                          float* As2, float* Bs, int tx, int ty) {
    ull c00 = 0, c01 = 0, c10 = 0, c11 = 0;
    for (int c = 0; c < nchunk; c++) {
        stageA_dup(A + (c << 7), lda, As2);
        stageB_T(B + (c << 7), ldb, Bs);
        __syncthreads();
        gemm_sh(As2, Bs, c00, c01, c10, c11, tx, ty);
        __syncthreads();
    }
    unpack_acc(c00, c01, c10, c11, acc);
}

// ------------------------- loop helpers (M=32 scalar-FFMA path) -------------
__device__ __forceinline__ void stage_loopA(const float* __restrict__ A, float* As) {
    const int r = threadIdx.x >> 4;        // 0..31
    const int q = threadIdx.x & 15;        // 8 floats each
    const float4* s = (const float4*)(A + (size_t)r * XD) + (q << 1);
    float4 v0 = __ldcg(s);
    float4 v1 = __ldcg(s + 1);
    *(float4*)&As[r * AS_STR + (q << 3) + 0] = v0;
    *(float4*)&As[r * AS_STR + (q << 3) + 4] = v1;
}

__device__ __forceinline__ void gemm32(const float* As, const float* Bs,
                                       float4& acc, int ty, int tx) {
    const float* ap = As + ty * AS_STR;
    const float* bp = Bs + (tx << 2);
#pragma unroll 4
    for (int k = 0; k < 128; k += 4) {
        float4 a = *(const float4*)(ap + k);
        float4 b0 = *(const float4*)(bp + (size_t)(k + 0) * WS_STRIDE);
        float4 b1 = *(const float4*)(bp + (size_t)(k + 1) * WS_STRIDE);
        float4 b2 = *(const float4*)(bp + (size_t)(k + 2) * WS_STRIDE);
        float4 b3 = *(const float4*)(bp + (size_t)(k + 3) * WS_STRIDE);
        acc.x += a.x * b0.x; acc.y += a.x * b0.y; acc.z += a.x * b0.z; acc.w += a.x * b0.w;
        acc.x += a.y * b1.x; acc.y += a.y * b1.y; acc.z += a.y * b1.z; acc.w += a.y * b1.w;
        acc.x += a.z * b2.x; acc.y += a.z * b2.y; acc.z += a.z * b2.z; acc.w += a.z * b2.w;
        acc.x += a.w * b3.x; acc.y += a.w * b3.y; acc.z += a.w * b3.z; acc.w += a.w * b3.w;
    }
}

__device__ __forceinline__ bool slab_pub(int slot, int sp, unsigned e, float4& acc) {
    const int off = (threadIdx.x >> 4) * 64 + ((threadIdx.x & 15) << 2);
    float* slab = g_part + ((size_t)slot * 8 + sp) * 2048;
    __stcg((float4*)(slab + off), acc);
    __syncthreads();
    __shared__ unsigned s_old;
    if (threadIdx.x == 0) s_old = atom_acqrel_add(&g_scnt[slot * 8]);
    __syncthreads();
    if (s_old != 8u * e - 1u) return false;
    float4 r = make_float4(0.f, 0.f, 0.f, 0.f);
    const float* base = g_part + (size_t)slot * 8 * 2048 + off;
#pragma unroll
    for (int sl = 0; sl < 8; sl++) {
        float4 v = __ldcg((const float4*)(base + sl * 2048));
        r.x += v.x; r.y += v.y; r.z += v.z; r.w += v.w;
    }
    acc = r;
    return true;
}

// ------------------------- main persistent kernel --------------------------
__global__ void __launch_bounds__(NTH, 1)
bnn_kernel(const float* __restrict__ x,
           const float* __restrict__ Wi,  const float* __restrict__ bi,
           const float* __restrict__ Wh1, const float* __restrict__ bh1,
           const float* __restrict__ Wh2, const float* __restrict__ bh2,
           const float* __restrict__ Wh3, const float* __restrict__ bh3,
           const float* __restrict__ Wo,  const float* __restrict__ bo,
           const float* __restrict__ Wr,  const float* __restrict__ br,
           const float* __restrict__ max_in,  const float* __restrict__ max_h1,
           const float* __restrict__ max_h2,  const float* __restrict__ max_h3,
           const float* __restrict__ max_out, const float* __restrict__ max_rec,
           const int* __restrict__ idx_in,  const int* __restrict__ idx_h1,
           const int* __restrict__ idx_h2,  const int* __restrict__ idx_h3,
           const int* __restrict__ idx_out, const int* __restrict__ idx_rec,
           float* __restrict__ out) {
    extern __shared__ float smem[];
    float* ws  = smem;                    // 4 persistent loop weight tiles / Bs scratch
    float* as2 = smem + 4 * WS_PHASE;     // precompute A staging / loop A staging

    const int bid = blockIdx.x;
    const int tid = threadIdx.x;
    const int tx  = tid & 15;
    const int ty  = tid >> 4;             // precompute: 2-row group | loop: row 0..31

    unsigned mygen = ((volatile unsigned*)&g_bargen)[0];

    // ---- init (every launch; FULL coverage — graph replays reuse state) ----
    for (int i = bid * NTH + tid; i < 2 * 32 * XD; i += NB * NTH) g_rs[i] = 0.0f;
    if (bid == 0) {
        for (int j = tid; j < 2 * 32 * 16; j += NTH) g_np[j] = 0.0f;
        for (int j = tid; j < 2 * 4 * 16 * 8; j += NTH) { g_scnt[j] = 0u; g_hcnt[j] = 0u; }
    }
    gsync(mygen);

    // ================= Phase A: actin = act(x @ Wi^T + bi), permuted =======
    for (int task = bid; task < 512 * 16; task += NB) {
        const int rt = task >> 4, nt2 = task & 15;
        float acc[2][4];
        gemm_task(x + (size_t)rt * 64 * IND, IND,
                  Wi + (size_t)(nt2 << 6) * IND, IND, 4, acc, as2, ws, tx, ty);
        const int col0 = (nt2 << 6) + (tx << 2);
        const int4   id4 = __ldg((const int4*)&idx_in[col0]);
        const float4 mx4 = __ldg((const float4*)&max_in[col0]);
        const float4 b4  = __ldg((const float4*)&bi[col0]);
#pragma unroll
        for (int i = 0; i < 2; i++) {
            const int g = rt * 64 + (ty << 1) + i;
            const int b = g >> 9, t = g & 511;
            float4 v = make_float4(acc[i][0] + b4.x, acc[i][1] + b4.y,
                                   acc[i][2] + b4.z, acc[i][3] + b4.w);
            v = act4(v, id4, mx4);
            __stcg((float4*)&g_actin[(size_t)(t * BB + b) * XD + col0], v);
        }
    }
    gsync(mygen);

    // ================= Phase B: P = actin @ Wh1a^T + bh1 ===================
    for (int task = bid; task < 512 * 16; task += NB) {
        const int rt = task >> 4, nt2 = task & 15;
        float acc[2][4];
        gemm_task(g_actin + (size_t)rt * 64 * XD, XD,
                  Wh1 + (size_t)(nt2 << 6) * (2 * XD), 2 * XD, 8, acc, as2, ws, tx, ty);
        const int col0 = (nt2 << 6) + (tx << 2);
        const float4 b4 = __ldg((const float4*)&bh1[col0]);
#pragma unroll
        for (int i = 0; i < 2; i++) {
            const int r = rt * 64 + (ty << 1) + i;
            float4 v = make_float4(acc[i][0] + b4.x, acc[i][1] + b4.y,
                                   acc[i][2] + b4.z, acc[i][3] + b4.w);
            __stcg((float4*)&g_P[(size_t)r * XD + col0], v);
        }
    }
    gsync(mygen);

    // ================= preload persistent loop weights =====================
    const int nt = bid >> 3;              // output tile 0..15
    const int sp = bid & 7;               // k-split 0..7
    const int n0 = nt << 6;
    const int k0 = sp << 7;
    const int col0 = n0 + (tx << 2);

    stageB_T(Wh1 + (size_t)n0 * (2 * XD) + XD + k0, 2 * XD, ws + 0 * WS_PHASE);
    stageB_T(Wh2 + (size_t)n0 * XD + k0,            XD,     ws + 1 * WS_PHASE);
    stageB_T(Wh3 + (size_t)n0 * XD + k0,            XD,     ws + 2 * WS_PHASE);
    stageB_T(Wr  + (size_t)n0 * XD + k0,            XD,     ws + 3 * WS_PHASE);
    __syncthreads();

    // per-phase epilogue tables
    const float* bias_tab[4] = { nullptr, bh2, bh3, br };
    const int*   idx_tab[4]  = { idx_h1, idx_h2, idx_h3, idx_rec };
    const float* mx_tab[4]   = { max_h1, max_h2, max_h3, max_rec };

    // ================= time loop: 2 interleaved batch chains ===============
    for (int s = 0; s < TT; s++) {
#pragma unroll 1
        for (int ph = 0; ph < 4; ph++) {
#pragma unroll 1
            for (int cc = 0; cc < 2; cc++) {
                // ---- wait on previous phase's 2 producer tiles ----
                const int prev = (ph + 3) & 3;
                const unsigned tgt = (ph == 0) ? (unsigned)s : (unsigned)(s + 1);
                waitcnt(&g_hcnt[((cc * 4 + prev) * 16 + 2 * sp) * 8],
                        &g_hcnt[((cc * 4 + prev) * 16 + 2 * sp + 1) * 8], tgt);

                // ---- stage A (32 x 128) ----
                const float* Asrc =
                    (ph == 0) ? g_rs + (size_t)cc * 32 * XD + k0 :
                    (ph == 1) ? g_h1 + (size_t)cc * 32 * XD + k0 :
                    (ph == 2) ? g_h2 + (size_t)cc * 32 * XD + k0 :
                                g_h3all + ((size_t)s * BB + 32 * cc) * XD + k0;
                stage_loopA(Asrc, as2);
                __syncthreads();

                // ---- gemm 32x64x128 ----
                float4 acc = make_float4(0.f, 0.f, 0.f, 0.f);
                gemm32(as2, ws + ph * WS_PHASE, acc, ty, tx);

                // ---- publish slab; 8th arriver does epilogue ----
                const int slot = (cc * 4 + ph) * 16 + nt;
                if (slab_pub(slot, sp, (unsigned)(s + 1), acc)) {
                    const int r = ty;                  // row within chain
                    const int4   id4 = __ldg((const int4*)&idx_tab[ph][col0]);
                    const float4 mx4 = __ldg((const float4*)&mx_tab[ph][col0]);
                    float4 v;
                    if (ph == 0) {
                        const float* npr = g_np + ((size_t)cc * 32 + r) * 16;
                        float4 n0v = __ldcg((const float4*)(npr + 0));
                        float4 n1v = __ldcg((const float4*)(npr + 4));
                        float4 n2v = __ldcg((const float4*)(npr + 8));
                        float4 n3v = __ldcg((const float4*)(npr + 12));
                        float ss = ((n0v.x + n0v.y) + (n0v.z + n0v.w))
                                 + ((n1v.x + n1v.y) + (n1v.z + n1v.w))
                                 + ((n2v.x + n2v.y) + (n2v.z + n2v.w))
                                 + ((n3v.x + n3v.y) + (n3v.z + n3v.w));
                        const float rinv = __fdividef(1.0f, fmaxf(__fsqrt_rn(ss), 1e-12f));
                        const float4 p4 = __ldcg((const float4*)
                            (g_P + ((size_t)s * BB + 32 * cc + r) * XD + col0));
                        v = make_float4(acc.x * rinv + p4.x, acc.y * rinv + p4.y,
                                        acc.z * rinv + p4.z, acc.w * rinv + p4.w);
                    } else {
                        const float4 b4 = __ldg((const float4*)&bias_tab[ph][col0]);
                        v = make_float4(acc.x + b4.x, acc.y + b4.y,
                                        acc.z + b4.z, acc.w + b4.w);
                    }
                    v = act4(v, id4, mx4);

                    if (ph == 0) {
                        __stcg((float4*)(g_h1 + ((size_t)cc * 32 + r) * XD + col0), v);
                    } else if (ph == 1) {
                        __stcg((float4*)(g_h2 + ((size_t)cc * 32 + r) * XD + col0), v);
                    } else if (ph == 2) {
                        __stcg((float4*)(g_h3all + ((size_t)s * BB + 32 * cc + r) * XD + col0), v);
                    } else {
                        __stcg((float4*)(g_rs + ((size_t)cc * 32 + r) * XD + col0), v);
                        float sq = v.x * v.x + v.y * v.y + v.z * v.z + v.w * v.w;
                        sq += __shfl_xor_sync(0xffffffffu, sq, 1, 16);
                        sq += __shfl_xor_sync(0xffffffffu, sq, 2, 16);
                        sq += __shfl_xor_sync(0xffffffffu, sq, 4, 16);
                        sq += __shfl_xor_sync(0xffffffffu, sq, 8, 16);
                        if (tx == 0) __stcg(&g_np[((size_t)cc * 32 + r) * 16 + nt], sq);
                    }
                    __syncthreads();
                    if (tid == 0) red_release_add(&g_hcnt[slot * 8]);
                }
            }
        }
    }
    gsync(mygen);

    // ================= Output GEMM: y = act(H3 @ Wo^T + bo) ================
    for (int task = bid; task < 512 * 4; task += NB) {
        const int t = task >> 2, ot = task & 3;
        float acc[2][4];
        gemm_task(g_h3all + (size_t)t * BB * XD, XD,
                  Wo + (size_t)(ot << 6) * XD, XD, 8, acc, as2, ws, tx, ty);
        const int oc0 = (ot << 6) + (tx << 2);
        const int4   id4 = __ldg((const int4*)&idx_out[oc0]);
        const float4 mx4 = __ldg((const float4*)&max_out[oc0]);
        const float4 b4  = __ldg((const float4*)&bo[oc0]);
#pragma unroll
        for (int i = 0; i < 2; i++) {
            const int b = (ty << 1) + i;
            float4 v = make_float4(acc[i][0] + b4.x, acc[i][1] + b4.y,
                                   acc[i][2] + b4.z, acc[i][3] + b4.w);
            v = act4(v, id4, mx4);
            __stcg((float4*)&out[((size_t)b * TT + t) * OUTD + oc0], v);
        }
    }
}

// ------------------------- launch ------------------------------------------
extern "C" void kernel_launch(void* const* d_in, const int* in_sizes, int n_in,
                              void* d_out, int out_size) {
    const float* x       = (const float*)d_in[0];
    const float* Wi      = (const float*)d_in[1];
    const float* bi      = (const float*)d_in[2];
    const float* Wh1     = (const float*)d_in[3];
    const float* bh1     = (const float*)d_in[4];
    const float* Wh2     = (const float*)d_in[5];
    const float* bh2     = (const float*)d_in[6];
    const float* Wh3     = (const float*)d_in[7];
    const float* bh3     = (const float*)d_in[8];
    const float* Wo      = (const float*)d_in[9];
    const float* bo      = (const float*)d_in[10];
    const float* Wr      = (const float*)d_in[11];
    const float* br      = (const float*)d_in[12];
    const float* max_in  = (const float*)d_in[13];
    const float* max_h1  = (const float*)d_in[14];
    const float* max_h2  = (const float*)d_in[15];
    const float* max_h3  = (const float*)d_in[16];
    const float* max_out = (const float*)d_in[17];
    const float* max_rec = (const float*)d_in[18];
    const int*   idx_in  = (const int*)d_in[19];
    const int*   idx_h1  = (const int*)d_in[20];
    const int*   idx_h2  = (const int*)d_in[21];
    const int*   idx_h3  = (const int*)d_in[22];
    const int*   idx_out = (const int*)d_in[23];
    const int*   idx_rec = (const int*)d_in[24];

    static int configured = 0;
    if (!configured) {
        cudaFuncSetAttribute(bnn_kernel, cudaFuncAttributeMaxDynamicSharedMemorySize,
                             SMEM_BYTES);
        configured = 1;
    }

    bnn_kernel<<<NB, NTH, SMEM_BYTES>>>(x, Wi, bi, Wh1, bh1, Wh2, bh2, Wh3, bh3,
                                        Wo, bo, Wr, br,
                                        max_in, max_h1, max_h2, max_h3, max_out, max_rec,
                                        idx_in, idx_h1, idx_h2, idx_h3, idx_out, idx_rec,
                                        (float*)d_out);
}